// round 1
// baseline (speedup 1.0000x reference)
#include <cuda_runtime.h>
#include <math.h>
#include <stdint.h>

// Problem dims
#define BDIM 1024
#define TDIM 1024
#define HDIM 128
#define CDIM 6
#define NBT  (BDIM * TDIM)

// ---------------- scratch: h for every (b, t), row = b*T + t ----------------
__device__ float g_h[(size_t)NBT * HDIM];   // 512 MB static device scratch

// ============================================================================
// Phase 1: recurrence. 128 CTAs x 256 threads, 8 batch rows per CTA.
// ============================================================================
#define WLD 385          // padded smem leading dim for transposed weights
#define R1  8            // rows per CTA

// smem layout (floats)
#define OFF_WHHT   0                         // 128 * 385
#define OFF_WIHT   (OFF_WHHT + 128 * WLD)    // 12 * 385
#define OFF_BIH    (OFF_WIHT + 12 * WLD)     // 384
#define OFF_BHH    (OFF_BIH + 384)           // 384
#define OFF_H      (OFF_BHH + 384)           // 8 * 128
#define OFF_GIN    (OFF_H + R1 * 128)        // 8 * 12
#define OFF_RUN    (OFF_GIN + R1 * 12)       // 8 * 6
#define OFF_XLAST  (OFF_RUN + R1 * 6)        // 8 * 6
#define OFF_DHW    (OFF_XLAST + R1 * 6)      // 128
#define OFF_DHB    (OFF_DHW + 128)           // 128
#define OFF_DXW    (OFF_DHB + 128)           // 8
#define OFF_DXB    (OFF_DXW + 8)             // 8
#define OFF_XMEAN  (OFF_DXB + 8)             // 8
#define SMEM1_FLOATS (OFF_XMEAN + 8)
#define SMEM1_BYTES  (SMEM1_FLOATS * 4)

__device__ __forceinline__ float fast_sigmoid(float x) {
    return __fdividef(1.0f, 1.0f + __expf(-x));
}

__global__ void __launch_bounds__(256, 1)
grud_recurrence_kernel(const float* __restrict__ x,
                       const float* __restrict__ x_mean,
                       const float* __restrict__ dxw,
                       const float* __restrict__ dxb,
                       const float* __restrict__ dhw,
                       const float* __restrict__ dhb,
                       const float* __restrict__ w_ih,
                       const float* __restrict__ w_hh,
                       const float* __restrict__ b_ih,
                       const float* __restrict__ b_hh) {
    extern __shared__ float sm[];
    float* s_whhT  = sm + OFF_WHHT;
    float* s_wihT  = sm + OFF_WIHT;
    float* s_bih   = sm + OFF_BIH;
    float* s_bhh   = sm + OFF_BHH;
    float* s_h     = sm + OFF_H;
    float* s_gin   = sm + OFF_GIN;
    float* s_run   = sm + OFF_RUN;
    float* s_xlast = sm + OFF_XLAST;
    float* s_dhw   = sm + OFF_DHW;
    float* s_dhb   = sm + OFF_DHB;
    float* s_dxw   = sm + OFF_DXW;
    float* s_dxb   = sm + OFF_DXB;
    float* s_xmean = sm + OFF_XMEAN;

    const int tid = threadIdx.x;

    // ---- load weights transposed (coalesced gmem read, conflict-free smem
    //      store thanks to the 385-float padded stride) ----
    for (int i = tid; i < 384 * 128; i += 256) {
        int o = i >> 7, k = i & 127;
        s_whhT[k * WLD + o] = w_hh[i];
    }
    for (int i = tid; i < 384 * 12; i += 256) {
        int o = i / 12, k = i % 12;
        s_wihT[k * WLD + o] = w_ih[i];
    }
    for (int i = tid; i < 384; i += 256) { s_bih[i] = b_ih[i]; s_bhh[i] = b_hh[i]; }
    for (int i = tid; i < 128; i += 256) { s_dhw[i] = dhw[i]; s_dhb[i] = dhb[i]; }
    if (tid < 6) { s_dxw[tid] = dxw[tid]; s_dxb[tid] = dxb[tid]; s_xmean[tid] = x_mean[tid]; }
    // init state
    for (int i = tid; i < R1 * 128; i += 256) s_h[i] = 0.0f;
    for (int i = tid; i < R1 * 6; i += 256) { s_run[i] = 0.0f; s_xlast[i] = 0.0f; }
    __syncthreads();

    const int warp = tid >> 5;
    const int lane = tid & 31;
    const int row_w = warp;                       // this warp's row (0..7)
    const int b_w = blockIdx.x * R1 + warp;       // global batch index
    const float* xrow = x + (size_t)b_w * TDIM * 13;

    // GEMM mapping: cb = neuron (0..127), rb = row-block (0..1)
    const int cb = tid & 127;
    const int rb = tid >> 7;
    const int r0 = rb * 4;

    // prefetch t = 0 inputs
    float xv_c = 0.0f, m_c = 0.0f, dt_c;
    dt_c = xrow[12];
    if (lane < 6) { xv_c = xrow[lane]; m_c = xrow[6 + lane]; }

    for (int t = 0; t < TDIM; ++t) {
        // ---------------- A: elementwise + h decay ----------------
        const float dt = dt_c;
        if (lane < 6) {
            const int c = lane;
            const float mm = m_c, xv = xv_c;
            const bool obs = mm > 0.5f;
            float run = obs ? 0.0f : (s_run[row_w * 6 + c] + dt);
            s_run[row_w * 6 + c] = run;
            float gx = __expf(-fmaxf(fmaf(run, s_dxw[c], s_dxb[c]), 0.0f));
            float xl = obs ? xv : s_xlast[row_w * 6 + c];
            s_xlast[row_w * 6 + c] = xl;
            float xh = mm * xv + (1.0f - mm) * (gx * xl + (1.0f - gx) * s_xmean[c]);
            s_gin[row_w * 12 + c] = xh;
            s_gin[row_w * 12 + 6 + c] = mm;
        }
        // h <- gamma_h * h  (each (row, j) touched by exactly one thread)
        #pragma unroll
        for (int jj = 0; jj < 4; ++jj) {
            int j = lane + 32 * jj;
            float g = __expf(-fmaxf(fmaf(dt, s_dhw[j], s_dhb[j]), 0.0f));
            s_h[row_w * 128 + j] *= g;
        }
        // prefetch next step's inputs (hidden behind the GEMM)
        if (t + 1 < TDIM) {
            const float* xr = xrow + (size_t)(t + 1) * 13;
            dt_c = xr[12];
            if (lane < 6) { xv_c = xr[lane]; m_c = xr[6 + lane]; }
        }
        __syncthreads();

        // ---------------- B: gi / gh GEMMs ----------------
        float ar[4], az[4], an[4];   // gi accumulators (r, z, n gates)
        float br[4], bz[4], bn[4];   // gh accumulators
        const float bihr = s_bih[cb], bihz = s_bih[cb + 128], bihn = s_bih[cb + 256];
        const float bhhr = s_bhh[cb], bhhz = s_bhh[cb + 128], bhhn = s_bhh[cb + 256];
        #pragma unroll
        for (int i = 0; i < 4; ++i) {
            ar[i] = bihr; az[i] = bihz; an[i] = bihn;
            br[i] = bhhr; bz[i] = bhhz; bn[i] = bhhn;
        }
        // gi: k over 12 (gru_in = [x_hat, m])
        #pragma unroll
        for (int k = 0; k < 12; ++k) {
            float wr = s_wihT[k * WLD + cb];
            float wz = s_wihT[k * WLD + cb + 128];
            float wn = s_wihT[k * WLD + cb + 256];
            #pragma unroll
            for (int i = 0; i < 4; ++i) {
                float g = s_gin[(r0 + i) * 12 + k];
                ar[i] = fmaf(wr, g, ar[i]);
                az[i] = fmaf(wz, g, az[i]);
                an[i] = fmaf(wn, g, an[i]);
            }
        }
        // gh: k over 128, float4 broadcast loads of h, scalar weight loads
        {
            const float4* h40 = (const float4*)(s_h + (r0 + 0) * 128);
            const float4* h41 = (const float4*)(s_h + (r0 + 1) * 128);
            const float4* h42 = (const float4*)(s_h + (r0 + 2) * 128);
            const float4* h43 = (const float4*)(s_h + (r0 + 3) * 128);
            for (int k4 = 0; k4 < 32; ++k4) {
                float4 v0 = h40[k4], v1 = h41[k4], v2 = h42[k4], v3 = h43[k4];
                float a0[4] = {v0.x, v0.y, v0.z, v0.w};
                float a1[4] = {v1.x, v1.y, v1.z, v1.w};
                float a2[4] = {v2.x, v2.y, v2.z, v2.w};
                float a3[4] = {v3.x, v3.y, v3.z, v3.w};
                #pragma unroll
                for (int kk = 0; kk < 4; ++kk) {
                    const int k = k4 * 4 + kk;
                    float wr = s_whhT[k * WLD + cb];
                    float wz = s_whhT[k * WLD + cb + 128];
                    float wn = s_whhT[k * WLD + cb + 256];
                    br[0] = fmaf(wr, a0[kk], br[0]); bz[0] = fmaf(wz, a0[kk], bz[0]); bn[0] = fmaf(wn, a0[kk], bn[0]);
                    br[1] = fmaf(wr, a1[kk], br[1]); bz[1] = fmaf(wz, a1[kk], bz[1]); bn[1] = fmaf(wn, a1[kk], bn[1]);
                    br[2] = fmaf(wr, a2[kk], br[2]); bz[2] = fmaf(wz, a2[kk], bz[2]); bn[2] = fmaf(wn, a2[kk], bn[2]);
                    br[3] = fmaf(wr, a3[kk], br[3]); bz[3] = fmaf(wz, a3[kk], bz[3]); bn[3] = fmaf(wn, a3[kk], bn[3]);
                }
            }
        }

        // ---------------- C: gates, h update, store ----------------
        float hnew[4];
        #pragma unroll
        for (int i = 0; i < 4; ++i) {
            float rr = fast_sigmoid(ar[i] + br[i]);
            float zz = fast_sigmoid(az[i] + bz[i]);
            float nn = tanhf(fmaf(rr, bn[i], an[i]));
            float hold = s_h[(r0 + i) * 128 + cb];
            hnew[i] = (1.0f - zz) * nn + zz * hold;
        }
        __syncthreads();   // all GEMM reads of s_h done before overwriting
        #pragma unroll
        for (int i = 0; i < 4; ++i) {
            s_h[(r0 + i) * 128 + cb] = hnew[i];
            const int bg = blockIdx.x * R1 + r0 + i;
            g_h[((size_t)bg * TDIM + t) * HDIM + cb] = hnew[i];
        }
        __syncthreads();   // writes visible before next step's decay
    }
}

// ============================================================================
// Phase 2: heads. Persistent 148 CTAs x 256 threads, 64-row tiles.
//   pred = relu(h @ w1^T + b1) @ w2^T + b2
//   unc  = softplus(relu(h @ wu1^T + bu1) @ wu2^T + bu2)
// ============================================================================
#define P2_TILE 64
#define W1LD 129
#define WULD 65
#define TLD  193

#define P2_W1T   0                          // 128 * 129
#define P2_WU1T  (P2_W1T + 128 * W1LD)      // 128 * 65
#define P2_W2    (P2_WU1T + 128 * WULD)     // 6 * 128
#define P2_WU2   (P2_W2 + 6 * 128)          // 6 * 64
#define P2_B1    (P2_WU2 + 6 * 64)          // 128
#define P2_BU1   (P2_B1 + 128)              // 64
#define P2_B2    (P2_BU1 + 64)              // 8
#define P2_BU2   (P2_B2 + 8)                // 8
#define P2_H     (P2_BU2 + 8)               // 64 * 128
#define P2_T     (P2_H + P2_TILE * 128)     // 64 * 193
#define SMEM2_FLOATS (P2_T + P2_TILE * TLD)
#define SMEM2_BYTES  (SMEM2_FLOATS * 4)

__device__ __forceinline__ float softplus_f(float x) {
    return fmaxf(x, 0.0f) + __logf(1.0f + __expf(-fabsf(x)));
}

__global__ void __launch_bounds__(256, 1)
grud_heads_kernel(const float* __restrict__ w1, const float* __restrict__ b1,
                  const float* __restrict__ w2, const float* __restrict__ b2,
                  const float* __restrict__ wu1, const float* __restrict__ bu1,
                  const float* __restrict__ wu2, const float* __restrict__ bu2,
                  float* __restrict__ out) {
    extern __shared__ float sm[];
    float* s_w1T  = sm + P2_W1T;
    float* s_wu1T = sm + P2_WU1T;
    float* s_w2   = sm + P2_W2;
    float* s_wu2  = sm + P2_WU2;
    float* s_b1   = sm + P2_B1;
    float* s_bu1  = sm + P2_BU1;
    float* s_b2   = sm + P2_B2;
    float* s_bu2  = sm + P2_BU2;
    float* s_h    = sm + P2_H;
    float* s_t    = sm + P2_T;

    const int tid = threadIdx.x;

    // weights once per CTA (transposed for stage-1 GEMM)
    for (int i = tid; i < 128 * 128; i += 256) {
        int o = i >> 7, k = i & 127;
        s_w1T[k * W1LD + o] = w1[i];
    }
    for (int i = tid; i < 64 * 128; i += 256) {
        int o = i >> 7, k = i & 127;
        s_wu1T[k * WULD + o] = wu1[i];
    }
    for (int i = tid; i < 6 * 128; i += 256) s_w2[i] = w2[i];
    for (int i = tid; i < 6 * 64; i += 256) s_wu2[i] = wu2[i];
    for (int i = tid; i < 128; i += 256) s_b1[i] = b1[i];
    for (int i = tid; i < 64; i += 256) s_bu1[i] = bu1[i];
    if (tid < 6) { s_b2[tid] = b2[tid]; s_bu2[tid] = bu2[tid]; }
    __syncthreads();

    const int cb = tid & 63;        // column within [0,64)
    const int rb = tid >> 6;        // row-block (0..3), 16 rows each
    const int NT = NBT / P2_TILE;   // 16384 tiles

    for (int tile = blockIdx.x; tile < NT; tile += gridDim.x) {
        const size_t row0 = (size_t)tile * P2_TILE;

        // load h tile (coalesced float4)
        {
            const float4* src = (const float4*)(g_h + row0 * HDIM);
            float4* dst = (float4*)s_h;
            for (int i = tid; i < P2_TILE * 128 / 4; i += 256) dst[i] = src[i];
        }
        __syncthreads();

        // stage 1: t1 (128 cols) and u1 (64 cols), 16 rows x 3 cols per thread
        float a1[16], a2[16], a3[16];
        {
            const float b1a = s_b1[cb], b1b = s_b1[cb + 64], bua = s_bu1[cb];
            #pragma unroll
            for (int i = 0; i < 16; ++i) { a1[i] = b1a; a2[i] = b1b; a3[i] = bua; }
            const float* hbase = s_h + rb * 16 * 128;
            for (int k4 = 0; k4 < 32; ++k4) {
                float w1a[4], w1b[4], wua[4];
                #pragma unroll
                for (int kk = 0; kk < 4; ++kk) {
                    const int k = k4 * 4 + kk;
                    w1a[kk] = s_w1T[k * W1LD + cb];
                    w1b[kk] = s_w1T[k * W1LD + cb + 64];
                    wua[kk] = s_wu1T[k * WULD + cb];
                }
                #pragma unroll
                for (int i = 0; i < 16; ++i) {
                    float4 v = *(const float4*)(hbase + i * 128 + k4 * 4);
                    a1[i] = fmaf(w1a[0], v.x, a1[i]); a1[i] = fmaf(w1a[1], v.y, a1[i]);
                    a1[i] = fmaf(w1a[2], v.z, a1[i]); a1[i] = fmaf(w1a[3], v.w, a1[i]);
                    a2[i] = fmaf(w1b[0], v.x, a2[i]); a2[i] = fmaf(w1b[1], v.y, a2[i]);
                    a2[i] = fmaf(w1b[2], v.z, a2[i]); a2[i] = fmaf(w1b[3], v.w, a2[i]);
                    a3[i] = fmaf(wua[0], v.x, a3[i]); a3[i] = fmaf(wua[1], v.y, a3[i]);
                    a3[i] = fmaf(wua[2], v.z, a3[i]); a3[i] = fmaf(wua[3], v.w, a3[i]);
                }
            }
        }
        __syncthreads();   // s_t may still be read from previous tile's stage 3
        #pragma unroll
        for (int i = 0; i < 16; ++i) {
            const int row = rb * 16 + i;
            s_t[row * TLD + cb]       = fmaxf(a1[i], 0.0f);
            s_t[row * TLD + 64 + cb]  = fmaxf(a2[i], 0.0f);
            s_t[row * TLD + 128 + cb] = fmaxf(a3[i], 0.0f);
        }
        __syncthreads();

        // stage 2: tiny output GEMMs + activations + global store
        for (int j = tid; j < P2_TILE * 12; j += 256) {
            const int row = j / 12;
            const int o = j % 12;
            const size_t rg = row0 + row;
            if (o < 6) {
                float s = s_b2[o];
                const float* tr = s_t + row * TLD;
                const float* wr = s_w2 + o * 128;
                #pragma unroll 8
                for (int k = 0; k < 128; ++k) s = fmaf(tr[k], wr[k], s);
                out[rg * 6 + o] = s;
            } else {
                const int oo = o - 6;
                float s = s_bu2[oo];
                const float* tr = s_t + row * TLD + 128;
                const float* wr = s_wu2 + oo * 64;
                #pragma unroll 8
                for (int k = 0; k < 64; ++k) s = fmaf(tr[k], wr[k], s);
                out[(size_t)NBT * 6 + rg * 6 + oo] = softplus_f(s);
            }
        }
        __syncthreads();   // protect s_h before next tile load
    }
}

// ============================================================================
// Launch
// ============================================================================
extern "C" void kernel_launch(void* const* d_in, const int* in_sizes, int n_in,
                              void* d_out, int out_size) {
    const float* x      = (const float*)d_in[0];
    const float* x_mean = (const float*)d_in[1];
    const float* dxw    = (const float*)d_in[2];
    const float* dxb    = (const float*)d_in[3];
    const float* dhw    = (const float*)d_in[4];
    const float* dhb    = (const float*)d_in[5];
    const float* w_ih   = (const float*)d_in[6];
    const float* w_hh   = (const float*)d_in[7];
    const float* b_ih   = (const float*)d_in[8];
    const float* b_hh   = (const float*)d_in[9];
    const float* w1     = (const float*)d_in[10];
    const float* b1     = (const float*)d_in[11];
    const float* w2     = (const float*)d_in[12];
    const float* b2     = (const float*)d_in[13];
    const float* wu1    = (const float*)d_in[14];
    const float* bu1    = (const float*)d_in[15];
    const float* wu2    = (const float*)d_in[16];
    const float* bu2    = (const float*)d_in[17];
    float* out = (float*)d_out;

    cudaFuncSetAttribute(grud_recurrence_kernel,
                         cudaFuncAttributeMaxDynamicSharedMemorySize, SMEM1_BYTES);
    cudaFuncSetAttribute(grud_heads_kernel,
                         cudaFuncAttributeMaxDynamicSharedMemorySize, SMEM2_BYTES);

    grud_recurrence_kernel<<<BDIM / R1, 256, SMEM1_BYTES>>>(
        x, x_mean, dxw, dxb, dhw, dhb, w_ih, w_hh, b_ih, b_hh);
    grud_heads_kernel<<<148, 256, SMEM2_BYTES>>>(
        w1, b1, w2, b2, wu1, bu1, wu2, bu2, out);
}

// round 2
// speedup vs baseline: 1.0030x; 1.0030x over previous
#include <cuda_runtime.h>
#include <math.h>
#include <stdint.h>

// Problem dims
#define BDIM 1024
#define TDIM 1024
#define HDIM 128
#define CDIM 6
#define NBT  (BDIM * TDIM)

// ---------------- scratch: h for every (b, t), row = b*T + t ----------------
__device__ float g_h[(size_t)NBT * HDIM];   // 512 MB static device scratch

// ============================================================================
// Phase 1: recurrence. 128 CTAs x 256 threads, 8 batch rows per CTA.
// ============================================================================
#define WLD 385          // padded smem leading dim for transposed weights
#define R1  8            // rows per CTA

// smem layout (floats)
#define OFF_WHHT   0                         // 128 * 385
#define OFF_WIHT   (OFF_WHHT + 128 * WLD)    // 12 * 385
#define OFF_BIH    (OFF_WIHT + 12 * WLD)     // 384
#define OFF_BHH    (OFF_BIH + 384)           // 384
#define OFF_H      (OFF_BHH + 384)           // 8 * 128
#define OFF_GIN    (OFF_H + R1 * 128)        // 8 * 12
#define OFF_RUN    (OFF_GIN + R1 * 12)       // 8 * 6
#define OFF_XLAST  (OFF_RUN + R1 * 6)        // 8 * 6
#define OFF_DHW    (OFF_XLAST + R1 * 6)      // 128
#define OFF_DHB    (OFF_DHW + 128)           // 128
#define OFF_DXW    (OFF_DHB + 128)           // 8
#define OFF_DXB    (OFF_DXW + 8)             // 8
#define OFF_XMEAN  (OFF_DXB + 8)             // 8
#define SMEM1_FLOATS (OFF_XMEAN + 8)
#define SMEM1_BYTES  (SMEM1_FLOATS * 4)

__device__ __forceinline__ float fast_sigmoid(float x) {
    return __fdividef(1.0f, 1.0f + __expf(-x));
}

__global__ void __launch_bounds__(256, 1)
grud_recurrence_kernel(const float* __restrict__ x,
                       const float* __restrict__ x_mean,
                       const float* __restrict__ dxw,
                       const float* __restrict__ dxb,
                       const float* __restrict__ dhw,
                       const float* __restrict__ dhb,
                       const float* __restrict__ w_ih,
                       const float* __restrict__ w_hh,
                       const float* __restrict__ b_ih,
                       const float* __restrict__ b_hh) {
    extern __shared__ float sm[];
    float* s_whhT  = sm + OFF_WHHT;
    float* s_wihT  = sm + OFF_WIHT;
    float* s_bih   = sm + OFF_BIH;
    float* s_bhh   = sm + OFF_BHH;
    float* s_h     = sm + OFF_H;
    float* s_gin   = sm + OFF_GIN;
    float* s_run   = sm + OFF_RUN;
    float* s_xlast = sm + OFF_XLAST;
    float* s_dhw   = sm + OFF_DHW;
    float* s_dhb   = sm + OFF_DHB;
    float* s_dxw   = sm + OFF_DXW;
    float* s_dxb   = sm + OFF_DXB;
    float* s_xmean = sm + OFF_XMEAN;

    const int tid = threadIdx.x;

    // ---- load weights transposed (coalesced gmem read, conflict-free smem
    //      store thanks to the 385-float padded stride) ----
    for (int i = tid; i < 384 * 128; i += 256) {
        int o = i >> 7, k = i & 127;
        s_whhT[k * WLD + o] = w_hh[i];
    }
    for (int i = tid; i < 384 * 12; i += 256) {
        int o = i / 12, k = i % 12;
        s_wihT[k * WLD + o] = w_ih[i];
    }
    for (int i = tid; i < 384; i += 256) { s_bih[i] = b_ih[i]; s_bhh[i] = b_hh[i]; }
    for (int i = tid; i < 128; i += 256) { s_dhw[i] = dhw[i]; s_dhb[i] = dhb[i]; }
    if (tid < 6) { s_dxw[tid] = dxw[tid]; s_dxb[tid] = dxb[tid]; s_xmean[tid] = x_mean[tid]; }
    // init state
    for (int i = tid; i < R1 * 128; i += 256) s_h[i] = 0.0f;
    for (int i = tid; i < R1 * 6; i += 256) { s_run[i] = 0.0f; s_xlast[i] = 0.0f; }
    __syncthreads();

    const int warp = tid >> 5;
    const int lane = tid & 31;
    const int row_w = warp;                       // this warp's row (0..7)
    const int b_w = blockIdx.x * R1 + warp;       // global batch index
    const float* xrow = x + (size_t)b_w * TDIM * 13;

    // GEMM mapping: cb = neuron (0..127), rb = row-block (0..1)
    const int cb = tid & 127;
    const int rb = tid >> 7;
    const int r0 = rb * 4;

    // prefetch t = 0 inputs
    float xv_c = 0.0f, m_c = 0.0f, dt_c;
    dt_c = xrow[12];
    if (lane < 6) { xv_c = xrow[lane]; m_c = xrow[6 + lane]; }

    for (int t = 0; t < TDIM; ++t) {
        // ---------------- A: elementwise + h decay ----------------
        const float dt = dt_c;
        if (lane < 6) {
            const int c = lane;
            const float mm = m_c, xv = xv_c;
            const bool obs = mm > 0.5f;
            float run = obs ? 0.0f : (s_run[row_w * 6 + c] + dt);
            s_run[row_w * 6 + c] = run;
            float gx = __expf(-fmaxf(fmaf(run, s_dxw[c], s_dxb[c]), 0.0f));
            float xl = obs ? xv : s_xlast[row_w * 6 + c];
            s_xlast[row_w * 6 + c] = xl;
            float xh = mm * xv + (1.0f - mm) * (gx * xl + (1.0f - gx) * s_xmean[c]);
            s_gin[row_w * 12 + c] = xh;
            s_gin[row_w * 12 + 6 + c] = mm;
        }
        // h <- gamma_h * h  (each (row, j) touched by exactly one thread)
        #pragma unroll
        for (int jj = 0; jj < 4; ++jj) {
            int j = lane + 32 * jj;
            float g = __expf(-fmaxf(fmaf(dt, s_dhw[j], s_dhb[j]), 0.0f));
            s_h[row_w * 128 + j] *= g;
        }
        // prefetch next step's inputs (hidden behind the GEMM)
        if (t + 1 < TDIM) {
            const float* xr = xrow + (size_t)(t + 1) * 13;
            dt_c = xr[12];
            if (lane < 6) { xv_c = xr[lane]; m_c = xr[6 + lane]; }
        }
        __syncthreads();

        // ---------------- B: gi / gh GEMMs ----------------
        float ar[4], az[4], an[4];   // gi accumulators (r, z, n gates)
        float br[4], bz[4], bn[4];   // gh accumulators
        const float bihr = s_bih[cb], bihz = s_bih[cb + 128], bihn = s_bih[cb + 256];
        const float bhhr = s_bhh[cb], bhhz = s_bhh[cb + 128], bhhn = s_bhh[cb + 256];
        #pragma unroll
        for (int i = 0; i < 4; ++i) {
            ar[i] = bihr; az[i] = bihz; an[i] = bihn;
            br[i] = bhhr; bz[i] = bhhz; bn[i] = bhhn;
        }
        // gi: k over 12 (gru_in = [x_hat, m])
        #pragma unroll
        for (int k = 0; k < 12; ++k) {
            float wr = s_wihT[k * WLD + cb];
            float wz = s_wihT[k * WLD + cb + 128];
            float wn = s_wihT[k * WLD + cb + 256];
            #pragma unroll
            for (int i = 0; i < 4; ++i) {
                float g = s_gin[(r0 + i) * 12 + k];
                ar[i] = fmaf(wr, g, ar[i]);
                az[i] = fmaf(wz, g, az[i]);
                an[i] = fmaf(wn, g, an[i]);
            }
        }
        // gh: k over 128, float4 broadcast loads of h, scalar weight loads
        {
            const float4* h40 = (const float4*)(s_h + (r0 + 0) * 128);
            const float4* h41 = (const float4*)(s_h + (r0 + 1) * 128);
            const float4* h42 = (const float4*)(s_h + (r0 + 2) * 128);
            const float4* h43 = (const float4*)(s_h + (r0 + 3) * 128);
            for (int k4 = 0; k4 < 32; ++k4) {
                float4 v0 = h40[k4], v1 = h41[k4], v2 = h42[k4], v3 = h43[k4];
                float a0[4] = {v0.x, v0.y, v0.z, v0.w};
                float a1[4] = {v1.x, v1.y, v1.z, v1.w};
                float a2[4] = {v2.x, v2.y, v2.z, v2.w};
                float a3[4] = {v3.x, v3.y, v3.z, v3.w};
                #pragma unroll
                for (int kk = 0; kk < 4; ++kk) {
                    const int k = k4 * 4 + kk;
                    float wr = s_whhT[k * WLD + cb];
                    float wz = s_whhT[k * WLD + cb + 128];
                    float wn = s_whhT[k * WLD + cb + 256];
                    br[0] = fmaf(wr, a0[kk], br[0]); bz[0] = fmaf(wz, a0[kk], bz[0]); bn[0] = fmaf(wn, a0[kk], bn[0]);
                    br[1] = fmaf(wr, a1[kk], br[1]); bz[1] = fmaf(wz, a1[kk], bz[1]); bn[1] = fmaf(wn, a1[kk], bn[1]);
                    br[2] = fmaf(wr, a2[kk], br[2]); bz[2] = fmaf(wz, a2[kk], bz[2]); bn[2] = fmaf(wn, a2[kk], bn[2]);
                    br[3] = fmaf(wr, a3[kk], br[3]); bz[3] = fmaf(wz, a3[kk], bz[3]); bn[3] = fmaf(wn, a3[kk], bn[3]);
                }
            }
        }

        // ---------------- C: gates, h update, store ----------------
        float hnew[4];
        #pragma unroll
        for (int i = 0; i < 4; ++i) {
            float rr = fast_sigmoid(ar[i] + br[i]);
            float zz = fast_sigmoid(az[i] + bz[i]);
            float nn = tanhf(fmaf(rr, bn[i], an[i]));
            float hold = s_h[(r0 + i) * 128 + cb];
            hnew[i] = (1.0f - zz) * nn + zz * hold;
        }
        __syncthreads();   // all GEMM reads of s_h done before overwriting
        #pragma unroll
        for (int i = 0; i < 4; ++i) {
            s_h[(r0 + i) * 128 + cb] = hnew[i];
            const int bg = blockIdx.x * R1 + r0 + i;
            g_h[((size_t)bg * TDIM + t) * HDIM + cb] = hnew[i];
        }
        __syncthreads();   // writes visible before next step's decay
    }
}

// ============================================================================
// Phase 2: heads. Persistent 148 CTAs x 256 threads, 64-row tiles.
//   pred = relu(h @ w1^T + b1) @ w2^T + b2
//   unc  = softplus(relu(h @ wu1^T + bu1) @ wu2^T + bu2)
// ============================================================================
#define P2_TILE 64
#define W1LD 129
#define WULD 65
#define TLD  193

#define P2_W1T   0                          // 128 * 129
#define P2_WU1T  (P2_W1T + 128 * W1LD)      // 128 * 65
#define P2_W2    (P2_WU1T + 128 * WULD)     // 6 * 128
#define P2_WU2   (P2_W2 + 6 * 128)          // 6 * 64
#define P2_B1    (P2_WU2 + 6 * 64)          // 128
#define P2_BU1   (P2_B1 + 128)              // 64
#define P2_B2    (P2_BU1 + 64)              // 8
#define P2_BU2   (P2_B2 + 8)                // 8
#define P2_H     (P2_BU2 + 8)               // 64 * 128
#define P2_T     (P2_H + P2_TILE * 128)     // 64 * 193
#define SMEM2_FLOATS (P2_T + P2_TILE * TLD)
#define SMEM2_BYTES  (SMEM2_FLOATS * 4)

__device__ __forceinline__ float softplus_f(float x) {
    return fmaxf(x, 0.0f) + __logf(1.0f + __expf(-fabsf(x)));
}

__global__ void __launch_bounds__(256, 1)
grud_heads_kernel(const float* __restrict__ w1, const float* __restrict__ b1,
                  const float* __restrict__ w2, const float* __restrict__ b2,
                  const float* __restrict__ wu1, const float* __restrict__ bu1,
                  const float* __restrict__ wu2, const float* __restrict__ bu2,
                  float* __restrict__ out) {
    extern __shared__ float sm[];
    float* s_w1T  = sm + P2_W1T;
    float* s_wu1T = sm + P2_WU1T;
    float* s_w2   = sm + P2_W2;
    float* s_wu2  = sm + P2_WU2;
    float* s_b1   = sm + P2_B1;
    float* s_bu1  = sm + P2_BU1;
    float* s_b2   = sm + P2_B2;
    float* s_bu2  = sm + P2_BU2;
    float* s_h    = sm + P2_H;
    float* s_t    = sm + P2_T;

    const int tid = threadIdx.x;

    // weights once per CTA (transposed for stage-1 GEMM)
    for (int i = tid; i < 128 * 128; i += 256) {
        int o = i >> 7, k = i & 127;
        s_w1T[k * W1LD + o] = w1[i];
    }
    for (int i = tid; i < 64 * 128; i += 256) {
        int o = i >> 7, k = i & 127;
        s_wu1T[k * WULD + o] = wu1[i];
    }
    for (int i = tid; i < 6 * 128; i += 256) s_w2[i] = w2[i];
    for (int i = tid; i < 6 * 64; i += 256) s_wu2[i] = wu2[i];
    for (int i = tid; i < 128; i += 256) s_b1[i] = b1[i];
    for (int i = tid; i < 64; i += 256) s_bu1[i] = bu1[i];
    if (tid < 6) { s_b2[tid] = b2[tid]; s_bu2[tid] = bu2[tid]; }
    __syncthreads();

    const int cb = tid & 63;        // column within [0,64)
    const int rb = tid >> 6;        // row-block (0..3), 16 rows each
    const int NT = NBT / P2_TILE;   // 16384 tiles

    for (int tile = blockIdx.x; tile < NT; tile += gridDim.x) {
        const size_t row0 = (size_t)tile * P2_TILE;

        // load h tile (coalesced float4)
        {
            const float4* src = (const float4*)(g_h + row0 * HDIM);
            float4* dst = (float4*)s_h;
            for (int i = tid; i < P2_TILE * 128 / 4; i += 256) dst[i] = src[i];
        }
        __syncthreads();

        // stage 1: t1 (128 cols) and u1 (64 cols), 16 rows x 3 cols per thread
        float a1[16], a2[16], a3[16];
        {
            const float b1a = s_b1[cb], b1b = s_b1[cb + 64], bua = s_bu1[cb];
            #pragma unroll
            for (int i = 0; i < 16; ++i) { a1[i] = b1a; a2[i] = b1b; a3[i] = bua; }
            const float* hbase = s_h + rb * 16 * 128;
            for (int k4 = 0; k4 < 32; ++k4) {
                float w1a[4], w1b[4], wua[4];
                #pragma unroll
                for (int kk = 0; kk < 4; ++kk) {
                    const int k = k4 * 4 + kk;
                    w1a[kk] = s_w1T[k * W1LD + cb];
                    w1b[kk] = s_w1T[k * W1LD + cb + 64];
                    wua[kk] = s_wu1T[k * WULD + cb];
                }
                #pragma unroll
                for (int i = 0; i < 16; ++i) {
                    float4 v = *(const float4*)(hbase + i * 128 + k4 * 4);
                    a1[i] = fmaf(w1a[0], v.x, a1[i]); a1[i] = fmaf(w1a[1], v.y, a1[i]);
                    a1[i] = fmaf(w1a[2], v.z, a1[i]); a1[i] = fmaf(w1a[3], v.w, a1[i]);
                    a2[i] = fmaf(w1b[0], v.x, a2[i]); a2[i] = fmaf(w1b[1], v.y, a2[i]);
                    a2[i] = fmaf(w1b[2], v.z, a2[i]); a2[i] = fmaf(w1b[3], v.w, a2[i]);
                    a3[i] = fmaf(wua[0], v.x, a3[i]); a3[i] = fmaf(wua[1], v.y, a3[i]);
                    a3[i] = fmaf(wua[2], v.z, a3[i]); a3[i] = fmaf(wua[3], v.w, a3[i]);
                }
            }
        }
        __syncthreads();   // s_t may still be read from previous tile's stage 3
        #pragma unroll
        for (int i = 0; i < 16; ++i) {
            const int row = rb * 16 + i;
            s_t[row * TLD + cb]       = fmaxf(a1[i], 0.0f);
            s_t[row * TLD + 64 + cb]  = fmaxf(a2[i], 0.0f);
            s_t[row * TLD + 128 + cb] = fmaxf(a3[i], 0.0f);
        }
        __syncthreads();

        // stage 2: tiny output GEMMs + activations + global store
        for (int j = tid; j < P2_TILE * 12; j += 256) {
            const int row = j / 12;
            const int o = j % 12;
            const size_t rg = row0 + row;
            if (o < 6) {
                float s = s_b2[o];
                const float* tr = s_t + row * TLD;
                const float* wr = s_w2 + o * 128;
                #pragma unroll 8
                for (int k = 0; k < 128; ++k) s = fmaf(tr[k], wr[k], s);
                out[rg * 6 + o] = s;
            } else {
                const int oo = o - 6;
                float s = s_bu2[oo];
                const float* tr = s_t + row * TLD + 128;
                const float* wr = s_wu2 + oo * 64;
                #pragma unroll 8
                for (int k = 0; k < 64; ++k) s = fmaf(tr[k], wr[k], s);
                out[(size_t)NBT * 6 + rg * 6 + oo] = softplus_f(s);
            }
        }
        __syncthreads();   // protect s_h before next tile load
    }
}

// ============================================================================
// Launch
// ============================================================================
extern "C" void kernel_launch(void* const* d_in, const int* in_sizes, int n_in,
                              void* d_out, int out_size) {
    const float* x      = (const float*)d_in[0];
    const float* x_mean = (const float*)d_in[1];
    const float* dxw    = (const float*)d_in[2];
    const float* dxb    = (const float*)d_in[3];
    const float* dhw    = (const float*)d_in[4];
    const float* dhb    = (const float*)d_in[5];
    const float* w_ih   = (const float*)d_in[6];
    const float* w_hh   = (const float*)d_in[7];
    const float* b_ih   = (const float*)d_in[8];
    const float* b_hh   = (const float*)d_in[9];
    const float* w1     = (const float*)d_in[10];
    const float* b1     = (const float*)d_in[11];
    const float* w2     = (const float*)d_in[12];
    const float* b2     = (const float*)d_in[13];
    const float* wu1    = (const float*)d_in[14];
    const float* bu1    = (const float*)d_in[15];
    const float* wu2    = (const float*)d_in[16];
    const float* bu2    = (const float*)d_in[17];
    float* out = (float*)d_out;

    cudaFuncSetAttribute(grud_recurrence_kernel,
                         cudaFuncAttributeMaxDynamicSharedMemorySize, SMEM1_BYTES);
    cudaFuncSetAttribute(grud_heads_kernel,
                         cudaFuncAttributeMaxDynamicSharedMemorySize, SMEM2_BYTES);

    grud_recurrence_kernel<<<BDIM / R1, 256, SMEM1_BYTES>>>(
        x, x_mean, dxw, dxb, dhw, dhb, w_ih, w_hh, b_ih, b_hh);
    grud_heads_kernel<<<148, 256, SMEM2_BYTES>>>(
        w1, b1, w2, b2, wu1, bu1, wu2, bu2, out);
}